// round 2
// baseline (speedup 1.0000x reference)
#include <cuda_runtime.h>

// Problem constants
#define IMG_W 512
#define IMG_H 512
#define HW (IMG_W * IMG_H)       // 262144
#define NCH 8
#define CHW (NCH * HW)           // 2097152
#define NB 16

// Tile: 32 wide x 16 tall interior, +1 halo each side
#define TLW 32
#define TLH 16
#define SW 34
#define SH 18
#define SCH (SW * SH)            // 612 elements per channel
#define SALL (NCH * SCH)         // 4896
#define NTHREADS 256

__device__ double g_acc;

__global__ void bicon_init_kernel() { g_acc = 0.0; }

__global__ void bicon_fin_kernel(float* out) { out[0] = (float)g_acc; }

__global__ __launch_bounds__(NTHREADS)
void bicon_main_kernel(const float* __restrict__ cmap,
                       const float* __restrict__ target,
                       const float* __restrict__ con)
{
    __shared__ float sp[SALL];   // sigmoid(p) tile, 0 for out-of-bounds
    __shared__ float slp[SALL];  // log(p) tile, -1e30 for out-of-bounds
    __shared__ double sred[NTHREADS / 32];

    const int b  = blockIdx.z;
    const int w0 = blockIdx.x * TLW;
    const int h0 = blockIdx.y * TLH;
    const int tid = threadIdx.x;

    const float* cb   = cmap   + (size_t)b * CHW;
    const float* conb = con    + (size_t)b * CHW;
    const float* tb   = target + (size_t)b * HW;

    float acc_con = 0.0f;
    float acc_bi  = 0.0f;
    float acc_de  = 0.0f;

    // ---------------- Phase 1: load halo tile, compute sigmoid + log once ----------
    // Also fold the conmap BCE for interior elements here using log(1-p) = log(p) - x.
    for (int i = tid; i < SALL; i += NTHREADS) {
        const int c  = i / SCH;
        const int r  = i - c * SCH;
        const int hl = r / SW;
        const int wl = r - hl * SW;
        const int h  = h0 + hl - 1;
        const int w  = w0 + wl - 1;

        float p, lp;
        if ((unsigned)h < (unsigned)IMG_H && (unsigned)w < (unsigned)IMG_W) {
            const int gidx = c * HW + h * IMG_W + w;
            const float x = cb[gidx];
            const float e = __expf(-x);
            p  = 1.0f / (1.0f + e);
            lp = __logf(p);
            // interior of this tile -> accumulate conmap BCE exactly once globally
            if (hl >= 1 && hl <= TLH && wl >= 1 && wl <= TLW) {
                const float t  = conb[gidx];
                const float Lp = fmaxf(lp, -100.0f);
                const float L1 = fmaxf(lp - x, -100.0f); // log(1-p) identity
                acc_con -= t * Lp + (1.0f - t) * L1;
            }
        } else {
            p  = 0.0f;     // padded neighbor: product a = 0
            lp = -1e30f;   // log(a) -> -inf -> clipped to -100 via fmaxf
        }
        sp[i]  = p;
        slp[i] = lp;
    }
    __syncthreads();

    // ---------------- Phase 2: stencil vote + bimap BCE + decouple BCE --------------
    const int tx = tid & 31;
    const int ty = tid >> 5;

#define SPV(c, hh, ww)  sp[(c) * SCH + (hh) * SW + (ww)]
#define SLV(c, hh, ww) slp[(c) * SCH + (hh) * SW + (ww)]

    #pragma unroll
    for (int jj = 0; jj < 2; jj++) {
        const int hl = 1 + ty + 8 * jj;
        const int wl = 1 + tx;
        const int h  = h0 + hl - 1;
        const int w  = w0 + wl - 1;

        const float p0 = SPV(0, hl, wl), p1 = SPV(1, hl, wl);
        const float p2 = SPV(2, hl, wl), p3 = SPV(3, hl, wl);
        const float p4 = SPV(4, hl, wl), p5 = SPV(5, hl, wl);
        const float p6 = SPV(6, hl, wl), p7 = SPV(7, hl, wl);
        const float l0 = SLV(0, hl, wl), l1 = SLV(1, hl, wl);
        const float l2 = SLV(2, hl, wl), l3 = SLV(3, hl, wl);
        const float l4 = SLV(4, hl, wl), l5 = SLV(5, hl, wl);
        const float l6 = SLV(6, hl, wl), l7 = SLV(7, hl, wl);

        // vote_out channel order: [a7, a3, a5, a1, a2, a6, a4, a8]
        float a[8], la[8];
        a[0] = p0 * SPV(7, hl - 1, wl - 1);  la[0] = l0 + SLV(7, hl - 1, wl - 1); // a7
        a[1] = p1 * SPV(6, hl - 1, wl    );  la[1] = l1 + SLV(6, hl - 1, wl    ); // a3
        a[2] = p2 * SPV(5, hl - 1, wl + 1);  la[2] = l2 + SLV(5, hl - 1, wl + 1); // a5
        a[3] = p3 * SPV(4, hl,     wl - 1);  la[3] = l3 + SLV(4, hl,     wl - 1); // a1
        a[4] = p4 * SPV(3, hl,     wl + 1);  la[4] = l4 + SLV(3, hl,     wl + 1); // a2
        a[5] = p5 * SPV(2, hl + 1, wl - 1);  la[5] = l5 + SLV(2, hl + 1, wl - 1); // a6
        a[6] = p6 * SPV(1, hl + 1, wl    );  la[6] = l6 + SLV(1, hl + 1, wl    ); // a4
        a[7] = p7 * SPV(0, hl + 1, wl + 1);  la[7] = l7 + SLV(0, hl + 1, wl + 1); // a8

        float asum = 0.0f, amin = 2.0f, sum_t = 0.0f;
        const int pbase = h * IMG_W + w;
        #pragma unroll
        for (int k = 0; k < 8; k++) {
            const float t   = conb[k * HW + pbase];
            const float La  = fmaxf(la[k], -100.0f);
            const float L1a = fmaxf(__logf(1.0f - a[k]), -100.0f);
            acc_bi -= t * La + (1.0f - t) * L1a;
            asum += a[k];
            amin  = fminf(amin, a[k]);
            sum_t += t;
        }

        const bool edge = (sum_t > 0.0f) && (sum_t < 8.0f);
        const float dc  = edge ? (1.0f - amin) : (asum * 0.125f);
        const float tg  = tb[pbase];
        const float Ld  = fmaxf(__logf(dc), -100.0f);
        const float L1d = fmaxf(__logf(1.0f - dc), -100.0f);
        acc_de -= tg * Ld + (1.0f - tg) * L1d;
    }

    // ---------------- Reduction: warp shuffle -> block double -> global atomic ------
    float part = 0.8f * acc_con + acc_de + 0.2f * acc_bi;
    #pragma unroll
    for (int o = 16; o > 0; o >>= 1)
        part += __shfl_xor_sync(0xffffffffu, part, o);
    if ((tid & 31) == 0)
        sred[tid >> 5] = (double)part;
    __syncthreads();
    if (tid == 0) {
        double s = 0.0;
        #pragma unroll
        for (int k = 0; k < NTHREADS / 32; k++) s += sred[k];
        atomicAdd(&g_acc, s);
    }
}

extern "C" void kernel_launch(void* const* d_in, const int* in_sizes, int n_in,
                              void* d_out, int out_size)
{
    const float* c_map      = (const float*)d_in[0];
    const float* target     = (const float*)d_in[1];
    const float* con_target = (const float*)d_in[2];
    float* out = (float*)d_out;

    bicon_init_kernel<<<1, 1>>>();
    dim3 grid(IMG_W / TLW, IMG_H / TLH, NB);  // 16 x 32 x 16
    bicon_main_kernel<<<grid, NTHREADS>>>(c_map, target, con_target);
    bicon_fin_kernel<<<1, 1>>>(out);
}

// round 3
// speedup vs baseline: 1.3093x; 1.3093x over previous
#include <cuda_runtime.h>

// Problem constants
#define IMG_W 512
#define IMG_H 512
#define HW (IMG_W * IMG_H)       // 262144
#define NCH 8
#define CHW (NCH * HW)           // 2097152
#define NB 16

// Tile: 32 wide x 16 tall interior, +1 halo each side
#define TLW 32
#define TLH 16
#define SW 34
#define SH 18
#define SCH (SW * SH)            // 612 elements per channel
#define SALL (NCH * SCH)         // 4896
#define NTHREADS 256
#define NBLK (16 * 32 * 16)      // 8192 blocks total

__device__ double g_part[NBLK];

__global__ __launch_bounds__(NTHREADS)
void bicon_main_kernel(const float* __restrict__ cmap,
                       const float* __restrict__ target,
                       const float* __restrict__ con)
{
    __shared__ float sp[SALL];                 // sigmoid(x), 0 for OOB
    __shared__ float slp[SALL];                // log(p), -1e30 for OOB
    __shared__ float sl1[NCH * TLH * TLW];     // clipped log(1-p), interior only
    __shared__ double sred[NTHREADS / 32];

    const int b  = blockIdx.z;
    const int w0 = blockIdx.x * TLW;
    const int h0 = blockIdx.y * TLH;
    const int tid = threadIdx.x;

    const float* cb   = cmap   + (size_t)b * CHW;
    const float* conb = con    + (size_t)b * CHW;
    const float* tb   = target + (size_t)b * HW;

    float acc_con = 0.0f;
    float acc_bi  = 0.0f;
    float acc_de  = 0.0f;

    // ---- Phase 1: load halo tile, compute sigmoid + log once (no con reads) ----
    #pragma unroll 4
    for (int i = tid; i < SALL; i += NTHREADS) {
        const int c  = i / SCH;
        const int r  = i - c * SCH;
        const int hl = r / SW;
        const int wl = r - hl * SW;
        const int h  = h0 + hl - 1;
        const int w  = w0 + wl - 1;

        float p, lp;
        if ((unsigned)h < (unsigned)IMG_H && (unsigned)w < (unsigned)IMG_W) {
            const float x = cb[c * HW + h * IMG_W + w];
            const float e = __expf(-x);
            const float s = 1.0f + e;
            p  = __fdividef(1.0f, s);      // sigmoid
            lp = -__logf(s);               // log(sigmoid) exactly (-log(1+e^-x))
            // interior -> also cache clipped log(1-p) = lp - x for conmap BCE
            if ((unsigned)(hl - 1) < (unsigned)TLH && (unsigned)(wl - 1) < (unsigned)TLW) {
                sl1[c * (TLH * TLW) + (hl - 1) * TLW + (wl - 1)] =
                    fmaxf(lp - x, -100.0f);
            }
        } else {
            p  = 0.0f;     // padded neighbor: product a = 0
            lp = -1e30f;   // log -> clipped to -100 via fmaxf later
        }
        sp[i]  = p;
        slp[i] = lp;
    }
    __syncthreads();

    // ---- Phase 2: stencil vote + all three BCE terms ----
    const int tx = tid & 31;
    const int ty = tid >> 5;

#define SPV(c, hh, ww)  sp[(c) * SCH + (hh) * SW + (ww)]
#define SLV(c, hh, ww) slp[(c) * SCH + (hh) * SW + (ww)]

    #pragma unroll
    for (int jj = 0; jj < 2; jj++) {
        const int hl = 1 + ty + 8 * jj;
        const int wl = 1 + tx;
        const int h  = h0 + hl - 1;
        const int w  = w0 + wl - 1;
        const int pbase = h * IMG_W + w;

        // Prefetch all global loads for this pixel (independent, high MLP)
        float t[8];
        #pragma unroll
        for (int k = 0; k < 8; k++) t[k] = conb[k * HW + pbase];
        const float tg = tb[pbase];

        const float p0 = SPV(0, hl, wl), p1 = SPV(1, hl, wl);
        const float p2 = SPV(2, hl, wl), p3 = SPV(3, hl, wl);
        const float p4 = SPV(4, hl, wl), p5 = SPV(5, hl, wl);
        const float p6 = SPV(6, hl, wl), p7 = SPV(7, hl, wl);
        const float l0 = SLV(0, hl, wl), l1 = SLV(1, hl, wl);
        const float l2 = SLV(2, hl, wl), l3 = SLV(3, hl, wl);
        const float l4 = SLV(4, hl, wl), l5 = SLV(5, hl, wl);
        const float l6 = SLV(6, hl, wl), l7 = SLV(7, hl, wl);

        // vote_out channel order: [a7, a3, a5, a1, a2, a6, a4, a8]
        float a[8], la[8];
        a[0] = p0 * SPV(7, hl - 1, wl - 1);  la[0] = l0 + SLV(7, hl - 1, wl - 1); // a7
        a[1] = p1 * SPV(6, hl - 1, wl    );  la[1] = l1 + SLV(6, hl - 1, wl    ); // a3
        a[2] = p2 * SPV(5, hl - 1, wl + 1);  la[2] = l2 + SLV(5, hl - 1, wl + 1); // a5
        a[3] = p3 * SPV(4, hl,     wl - 1);  la[3] = l3 + SLV(4, hl,     wl - 1); // a1
        a[4] = p4 * SPV(3, hl,     wl + 1);  la[4] = l4 + SLV(3, hl,     wl + 1); // a2
        a[5] = p5 * SPV(2, hl + 1, wl - 1);  la[5] = l5 + SLV(2, hl + 1, wl - 1); // a6
        a[6] = p6 * SPV(1, hl + 1, wl    );  la[6] = l6 + SLV(1, hl + 1, wl    ); // a4
        a[7] = p7 * SPV(0, hl + 1, wl + 1);  la[7] = l7 + SLV(0, hl + 1, wl + 1); // a8

        // center-channel clipped logs (vote order irrelevant for conmap sum)
        const float lc[8] = { l0, l1, l2, l3, l4, l5, l6, l7 };
        // con channel order for bimap matches vote order [a7,a3,a5,a1,a2,a6,a4,a8]
        // -> con channel of vote slot k:
        //    slot:   0  1  2  3  4  5  6  7
        //    t used: t[0..7] in natural order for conmap; for bimap the reference
        //    compares vote_out (stacked order) against con_target channels 0..7,
        //    so slot k pairs with t[k] directly.
        float asum = 0.0f, amin = 2.0f, sum_t = 0.0f;
        #pragma unroll
        for (int k = 0; k < 8; k++) {
            const float La  = fmaxf(la[k], -100.0f);
            const float L1a = fmaxf(__logf(1.0f - a[k]), -100.0f);
            acc_bi -= t[k] * La + (1.0f - t[k]) * L1a;
            // conmap BCE: channel k natural order
            const float Lp  = fmaxf(lc[k], -100.0f);
            const float L1p = sl1[k * (TLH * TLW) + (hl - 1) * TLW + (wl - 1)];
            acc_con -= t[k] * Lp + (1.0f - t[k]) * L1p;
            asum += a[k];
            amin  = fminf(amin, a[k]);
            sum_t += t[k];
        }

        const bool edge = (sum_t > 0.0f) && (sum_t < 8.0f);
        const float dc  = edge ? (1.0f - amin) : (asum * 0.125f);
        const float Ld  = fmaxf(__logf(dc), -100.0f);
        const float L1d = fmaxf(__logf(1.0f - dc), -100.0f);
        acc_de -= tg * Ld + (1.0f - tg) * L1d;
    }

    // ---- Reduction: warp shuffle -> block -> per-block partial (no atomics) ----
    float part = 0.8f * acc_con + acc_de + 0.2f * acc_bi;
    #pragma unroll
    for (int o = 16; o > 0; o >>= 1)
        part += __shfl_xor_sync(0xffffffffu, part, o);
    if ((tid & 31) == 0)
        sred[tid >> 5] = (double)part;
    __syncthreads();
    if (tid == 0) {
        double s = 0.0;
        #pragma unroll
        for (int k = 0; k < NTHREADS / 32; k++) s += sred[k];
        const int bid = (blockIdx.z * gridDim.y + blockIdx.y) * gridDim.x + blockIdx.x;
        g_part[bid] = s;
    }
}

__global__ __launch_bounds__(1024)
void bicon_reduce_kernel(float* out)
{
    __shared__ double s[32];
    const int tid = threadIdx.x;
    double a = 0.0;
    #pragma unroll
    for (int k = 0; k < NBLK / 1024; k++)
        a += g_part[tid + k * 1024];
    #pragma unroll
    for (int o = 16; o > 0; o >>= 1)
        a += __shfl_xor_sync(0xffffffffu, a, o);
    if ((tid & 31) == 0)
        s[tid >> 5] = a;
    __syncthreads();
    if (tid < 32) {
        double v = s[tid];
        #pragma unroll
        for (int o = 16; o > 0; o >>= 1)
            v += __shfl_xor_sync(0xffffffffu, v, o);
        if (tid == 0) out[0] = (float)v;
    }
}

extern "C" void kernel_launch(void* const* d_in, const int* in_sizes, int n_in,
                              void* d_out, int out_size)
{
    const float* c_map      = (const float*)d_in[0];
    const float* target     = (const float*)d_in[1];
    const float* con_target = (const float*)d_in[2];
    float* out = (float*)d_out;

    dim3 grid(IMG_W / TLW, IMG_H / TLH, NB);  // 16 x 32 x 16 = 8192
    bicon_main_kernel<<<grid, NTHREADS>>>(c_map, target, con_target);
    bicon_reduce_kernel<<<1, 1024>>>(out);
}

// round 5
// speedup vs baseline: 1.3189x; 1.0073x over previous
#include <cuda_runtime.h>

// Problem constants
#define IMG_W 512
#define IMG_H 512
#define HW (IMG_W * IMG_H)       // 262144
#define NCH 8
#define CHW (NCH * HW)           // 2097152
#define NB 16

// Tile: 32 wide x 16 tall interior, +1 halo each side
#define TLW 32
#define TLH 16
#define SW 34
#define SH 18
#define SCH (SW * SH)            // 612 elements per channel
#define SALL (NCH * SCH)         // 4896
#define NTHREADS 256
#define NBLK (16 * 32 * 16)      // 8192 blocks total
#define TILE (TLH * TLW)         // 512

__device__ double g_part[NBLK];

__global__ __launch_bounds__(NTHREADS, 4)
void bicon_main_kernel(const float* __restrict__ cmap,
                       const float* __restrict__ target,
                       const float* __restrict__ con)
{
    __shared__ float sp[SALL];          // sigmoid(x), 0 for OOB
    __shared__ float sD[NCH * TILE];    // clip(log p) - clip(log(1-p)), interior
    __shared__ double sred[NTHREADS / 32];

    const int b  = blockIdx.z;
    const int w0 = blockIdx.x * TLW;
    const int h0 = blockIdx.y * TLH;
    const int tid = threadIdx.x;

    const float* cb   = cmap   + (size_t)b * CHW;
    const float* conb = con    + (size_t)b * CHW;
    const float* tb   = target + (size_t)b * HW;

    float acc1   = 0.0f;  // conmap: t-independent part  (sum of -L1p)
    float acc_ct = 0.0f;  // conmap: -t*D part
    float acc_bi = 0.0f;
    float acc_de = 0.0f;

    // ---- Phase 1: load halo tile, sigmoid; interior also logs for conmap ----
    #pragma unroll 4
    for (int i = tid; i < SALL; i += NTHREADS) {
        const int c  = i / SCH;
        const int r  = i - c * SCH;
        const int hl = r / SW;
        const int wl = r - hl * SW;
        const int h  = h0 + hl - 1;
        const int w  = w0 + wl - 1;

        float p = 0.0f;  // OOB: product a = 0 downstream
        if ((unsigned)h < (unsigned)IMG_H && (unsigned)w < (unsigned)IMG_W) {
            const float x = cb[c * HW + h * IMG_W + w];
            const float e = __expf(-x);
            const float s = 1.0f + e;
            p = __fdividef(1.0f, s);                 // sigmoid
            if ((unsigned)(hl - 1) < (unsigned)TLH &&
                (unsigned)(wl - 1) < (unsigned)TLW) {
                const float lp  = -__logf(s);        // log(sigmoid), exact identity
                const float L1  = fmaxf(lp - x, -100.0f);   // clip(log(1-p))
                const float Lp  = fmaxf(lp, -100.0f);       // clip(log p)
                acc1 -= L1;                                 // t-independent conmap part
                sD[c * TILE + (hl - 1) * TLW + (wl - 1)] = Lp - L1;
            }
        }
        sp[i] = p;
    }
    __syncthreads();

    // ---- Phase 2: stencil vote + bimap + conmap(t part) + decouple BCE ----
    const int tx = tid & 31;
    const int ty = tid >> 5;
    const int wl = 1 + tx;

#define SPV(c, hh, ww)  sp[(c) * SCH + (hh) * SW + (ww)]

    // vote slot k: own channel k, neighbor channel 7-k, offset (dh[k], dw[k])
    static constexpr int dh[8] = { -1, -1, -1,  0,  0,  1,  1,  1 };
    static constexpr int dw[8] = { -1,  0,  1, -1,  1, -1,  0,  1 };

    #pragma unroll
    for (int jj = 0; jj < 2; jj++) {
        const int hl = 1 + ty + 8 * jj;
        const int pbase = (h0 + hl - 1) * IMG_W + (w0 + wl - 1);
        const int didx  = (hl - 1) * TLW + (wl - 1);
        const float* __restrict__ cp = conb + pbase;

        const float tg = tb[pbase];
        float asum = 0.0f, amin = 2.0f, sum_t = 0.0f;

        #pragma unroll
        for (int k = 0; k < 8; k++) {
            const float t = cp[k * HW];
            const float a = SPV(k, hl, wl) * SPV(7 - k, hl + dh[k], wl + dw[k]);
            const float La  = fmaxf(__logf(a), -100.0f);
            const float L1a = fmaxf(__logf(1.0f - a), -100.0f);
            acc_bi -= L1a + t * (La - L1a);
            acc_ct -= t * sD[k * TILE + didx];
            asum += a;
            amin  = fminf(amin, a);
            sum_t += t;
        }

        const bool edge = (sum_t > 0.0f) && (sum_t < 8.0f);
        const float dc  = edge ? (1.0f - amin) : (asum * 0.125f);
        const float Ld  = fmaxf(__logf(dc), -100.0f);
        const float L1d = fmaxf(__logf(1.0f - dc), -100.0f);
        acc_de -= tg * Ld + (1.0f - tg) * L1d;
    }

    // ---- Reduction: warp shuffle -> block -> per-block partial (no atomics) ----
    float part = 0.8f * (acc1 + acc_ct) + acc_de + 0.2f * acc_bi;
    #pragma unroll
    for (int o = 16; o > 0; o >>= 1)
        part += __shfl_xor_sync(0xffffffffu, part, o);
    if ((tid & 31) == 0)
        sred[tid >> 5] = (double)part;
    __syncthreads();
    if (tid == 0) {
        double s = 0.0;
        #pragma unroll
        for (int k = 0; k < NTHREADS / 32; k++) s += sred[k];
        const int bid = (blockIdx.z * gridDim.y + blockIdx.y) * gridDim.x + blockIdx.x;
        g_part[bid] = s;
    }
}

__global__ __launch_bounds__(1024)
void bicon_reduce_kernel(float* out)
{
    __shared__ double s[32];
    const int tid = threadIdx.x;
    double a = 0.0;
    #pragma unroll
    for (int k = 0; k < NBLK / 1024; k++)
        a += g_part[tid + k * 1024];
    #pragma unroll
    for (int o = 16; o > 0; o >>= 1)
        a += __shfl_xor_sync(0xffffffffu, a, o);
    if ((tid & 31) == 0)
        s[tid >> 5] = a;
    __syncthreads();
    if (tid < 32) {
        double v = s[tid];
        #pragma unroll
        for (int o = 16; o > 0; o >>= 1)
            v += __shfl_xor_sync(0xffffffffu, v, o);
        if (tid == 0) out[0] = (float)v;
    }
}

extern "C" void kernel_launch(void* const* d_in, const int* in_sizes, int n_in,
                              void* d_out, int out_size)
{
    const float* c_map      = (const float*)d_in[0];
    const float* target     = (const float*)d_in[1];
    const float* con_target = (const float*)d_in[2];
    float* out = (float*)d_out;

    dim3 grid(IMG_W / TLW, IMG_H / TLH, NB);  // 16 x 32 x 16 = 8192
    bicon_main_kernel<<<grid, NTHREADS>>>(c_map, target, con_target);
    bicon_reduce_kernel<<<1, 1024>>>(out);
}

// round 6
// speedup vs baseline: 2.2091x; 1.6750x over previous
#include <cuda_runtime.h>

// Problem constants
#define IMG_W 512
#define IMG_H 512
#define HW (IMG_W * IMG_H)       // 262144
#define NCH 8
#define CHW (NCH * HW)           // 2097152
#define NB 16

// Tile: 32 wide x 16 tall interior, +1 halo each side
#define TLW 32
#define TLH 16
#define SW 34
#define SH 18
#define SCH (SW * SH)            // 612 elements per channel
#define SALL (NCH * SCH)         // 4896
#define NTHREADS 256
#define NBLK (16 * 32 * 16)      // 8192 blocks total
#define TILE (TLH * TLW)         // 512
#define NLOAD ((SALL + NTHREADS - 1) / NTHREADS)   // 20

__device__ double g_part[NBLK];
__device__ unsigned int g_count = 0;   // reset by last block each call

__global__ __launch_bounds__(NTHREADS, 3)
void bicon_main_kernel(const float* __restrict__ cmap,
                       const float* __restrict__ target,
                       const float* __restrict__ con,
                       float* __restrict__ out)
{
    __shared__ float  sp[SALL];          // sigmoid(x), 0 for OOB
    __shared__ float  sD[NCH * TILE];    // clip(log p) - clip(log(1-p)), interior
    __shared__ double sred[NTHREADS / 32];
    __shared__ double sfin[NTHREADS];
    __shared__ int    s_last;

    const int b  = blockIdx.z;
    const int w0 = blockIdx.x * TLW;
    const int h0 = blockIdx.y * TLH;
    const int tid = threadIdx.x;

    const float* cb   = cmap   + (size_t)b * CHW;
    const float* conb = con    + (size_t)b * CHW;
    const float* tb   = target + (size_t)b * HW;

    // ---- Phase 1a: batched clamped loads (high MLP, no branches around LDG) ----
    float xv[NLOAD];
    #pragma unroll
    for (int j = 0; j < NLOAD; j++) {
        const int i  = tid + j * NTHREADS;
        const int c  = i / SCH;
        const int r  = i - c * SCH;
        const int hl = r / SW;
        const int wl = r - hl * SW;
        const int h  = h0 + hl - 1;
        const int w  = w0 + wl - 1;
        const int hc = min(max(h, 0), IMG_H - 1);
        const int wc = min(max(w, 0), IMG_W - 1);
        const int cc = min(c, NCH - 1);          // j=19 tail may run past SALL
        xv[j] = cb[cc * HW + hc * IMG_W + wc];
    }

    // ---- Phase 1b: sigmoid + logs, fill smem tiles ----
    float acc1 = 0.0f;   // conmap t-independent part: sum of -clip(log(1-p))
    #pragma unroll
    for (int j = 0; j < NLOAD; j++) {
        const int i = tid + j * NTHREADS;
        if (i < SALL) {
            const int c  = i / SCH;
            const int r  = i - c * SCH;
            const int hl = r / SW;
            const int wl = r - hl * SW;
            const int h  = h0 + hl - 1;
            const int w  = w0 + wl - 1;
            const bool valid    = ((unsigned)h < (unsigned)IMG_H) &
                                  ((unsigned)w < (unsigned)IMG_W);
            const bool interior = ((unsigned)(hl - 1) < (unsigned)TLH) &
                                  ((unsigned)(wl - 1) < (unsigned)TLW);

            const float x = xv[j];
            const float e = __expf(-x);
            const float s = 1.0f + e;
            float p = __fdividef(1.0f, s);           // sigmoid
            const float lp = -__logf(s);             // log(sigmoid), exact identity
            p = valid ? p : 0.0f;                    // OOB neighbor: product a = 0
            sp[i] = p;
            if (interior) {
                const float L1 = fmaxf(lp - x, -100.0f);   // clip(log(1-p))
                acc1 -= L1;
                sD[c * TILE + (hl - 1) * TLW + (wl - 1)] =
                    fmaxf(lp, -100.0f) - L1;
            }
        }
    }
    __syncthreads();

    // ---- Phase 2: stencil vote + bimap + conmap(t part) + decouple BCE ----
    const int tx = tid & 31;
    const int ty = tid >> 5;
    const int wl = 1 + tx;

#define SPV(c, hh, ww)  sp[(c) * SCH + (hh) * SW + (ww)]

    // vote slot k: own channel k, neighbor channel 7-k, offset (dh[k], dw[k])
    static constexpr int dh[8] = { -1, -1, -1,  0,  0,  1,  1,  1 };
    static constexpr int dw[8] = { -1,  0,  1, -1,  1, -1,  0,  1 };

    float acc_ct = 0.0f;
    float acc_bi = 0.0f;
    float acc_de = 0.0f;

    #pragma unroll
    for (int jj = 0; jj < 2; jj++) {
        const int hl = 1 + ty + 8 * jj;
        const int pbase = (h0 + hl - 1) * IMG_W + (w0 + wl - 1);
        const int didx  = (hl - 1) * TLW + (wl - 1);
        const float* __restrict__ cp = conb + pbase;

        // prefetch all 9 global values (independent loads, batched)
        float t[8];
        #pragma unroll
        for (int k = 0; k < 8; k++) t[k] = cp[k * HW];
        const float tg = tb[pbase];

        float asum = 0.0f, amin = 2.0f, sum_t = 0.0f;
        #pragma unroll
        for (int k = 0; k < 8; k++) {
            const float a = SPV(k, hl, wl) * SPV(7 - k, hl + dh[k], wl + dw[k]);
            // t is exactly 0.0 or 1.0 (bernoulli):
            //   -(t*clip(log a) + (1-t)*clip(log(1-a))) = -clip(log(t ? a : 1-a))
            const float sel = (t[k] > 0.5f) ? a : (1.0f - a);
            acc_bi -= fmaxf(__logf(sel), -100.0f);
            acc_ct -= t[k] * sD[k * TILE + didx];
            asum += a;
            amin  = fminf(amin, a);
            sum_t += t[k];
        }

        const bool edge = (sum_t > 0.0f) && (sum_t < 8.0f);
        const float dc  = edge ? (1.0f - amin) : (asum * 0.125f);
        const float dsel = (tg > 0.5f) ? dc : (1.0f - dc);
        acc_de -= fmaxf(__logf(dsel), -100.0f);
    }

    // ---- Block reduction: warp shuffle -> smem -> per-block double partial ----
    float part = 0.8f * (acc1 + acc_ct) + acc_de + 0.2f * acc_bi;
    #pragma unroll
    for (int o = 16; o > 0; o >>= 1)
        part += __shfl_xor_sync(0xffffffffu, part, o);
    if ((tid & 31) == 0)
        sred[tid >> 5] = (double)part;
    __syncthreads();

    const int bid = (blockIdx.z * gridDim.y + blockIdx.y) * gridDim.x + blockIdx.x;
    if (tid == 0) {
        double s = 0.0;
        #pragma unroll
        for (int k = 0; k < NTHREADS / 32; k++) s += sred[k];
        g_part[bid] = s;
        __threadfence();
        const unsigned ticket = atomicAdd(&g_count, 1u);
        s_last = (ticket == NBLK - 1) ? 1 : 0;
    }
    __syncthreads();

    // ---- Last block: final deterministic reduction over all partials ----
    if (s_last) {
        __threadfence();
        double a = 0.0;
        #pragma unroll
        for (int k = 0; k < NBLK / NTHREADS; k++)      // 32 each, fixed order
            a += g_part[tid + k * NTHREADS];
        sfin[tid] = a;
        __syncthreads();
        #pragma unroll
        for (int off = NTHREADS / 2; off > 0; off >>= 1) {
            if (tid < off) sfin[tid] += sfin[tid + off];
            __syncthreads();
        }
        if (tid == 0) {
            out[0] = (float)sfin[0];
            g_count = 0;    // re-arm for the next graph replay
        }
    }
}

extern "C" void kernel_launch(void* const* d_in, const int* in_sizes, int n_in,
                              void* d_out, int out_size)
{
    const float* c_map      = (const float*)d_in[0];
    const float* target     = (const float*)d_in[1];
    const float* con_target = (const float*)d_in[2];
    float* out = (float*)d_out;

    dim3 grid(IMG_W / TLW, IMG_H / TLH, NB);  // 16 x 32 x 16 = 8192
    bicon_main_kernel<<<grid, NTHREADS>>>(c_map, target, con_target, out);
}